// round 1
// baseline (speedup 1.0000x reference)
#include <cuda_runtime.h>
#include <math.h>

#define NN   1024
#define IND  128
#define OUTD 128
#define HH   4
#define DD   32
#define TJ   64
#define NT   (NN / TJ)      // 16 j-tiles
#define RPAD 132            // R_s row stride (floats): 16B aligned, conflict-free f4 reads
#define WPAD 68             // w_s row stride

// ---- scratch (static device arrays; no allocation) ----
__device__ __align__(16) float g_L[NN * OUTD];
__device__ __align__(16) float g_R[NN * OUTD];
__device__ __align__(16) float g_V[NN * OUTD];
__device__ __align__(16) float g_aR[NN * HH];

__constant__ float c_a[DD];

// =====================================================================
// Kernel 1: C = h @ W for W in {W_l, W_r, W_v}.  BM=32, BN=128, K=128.
// grid (32, 3), 256 threads.  smem = 32*128 + 128*128 floats = 80KB.
// =====================================================================
__global__ __launch_bounds__(256) void gemm_kernel(
    const float* __restrict__ H,
    const float* __restrict__ Wl,
    const float* __restrict__ Wr,
    const float* __restrict__ Wv)
{
    extern __shared__ float sm[];
    float* A_s = sm;              // [32][128]
    float* B_s = sm + 32 * 128;   // [128][128]

    const int tid = threadIdx.x;
    const int mat = blockIdx.y;
    const float* W = (mat == 0) ? Wl : ((mat == 1) ? Wr : Wv);
    float* C = (mat == 0) ? g_L : ((mat == 1) ? g_R : g_V);
    const int row0 = blockIdx.x * 32;

    // load A tile (32x128) — one float4 per thread per u
#pragma unroll
    for (int u = 0; u < 4; u++) {
        int id = tid + u * 256;        // float4 id in [0,1024)
        int r = id >> 5, c4 = id & 31;
        *(float4*)&A_s[r * 128 + c4 * 4] =
            *(const float4*)&H[(row0 + r) * IND + c4 * 4];
    }
    // load full W (128x128)
#pragma unroll
    for (int u = 0; u < 16; u++) {
        int id = tid + u * 256;        // [0,4096)
        int r = id >> 5, c4 = id & 31;
        *(float4*)&B_s[r * 128 + c4 * 4] =
            *(const float4*)&W[r * OUTD + c4 * 4];
    }
    __syncthreads();

    const int ty = tid >> 5, tx = tid & 31;
    float acc[4][4];
#pragma unroll
    for (int r = 0; r < 4; r++)
#pragma unroll
        for (int c = 0; c < 4; c++) acc[r][c] = 0.f;

#pragma unroll 8
    for (int k = 0; k < 128; k++) {
        float a0 = A_s[(ty * 4 + 0) * 128 + k];   // broadcast
        float a1 = A_s[(ty * 4 + 1) * 128 + k];
        float a2 = A_s[(ty * 4 + 2) * 128 + k];
        float a3 = A_s[(ty * 4 + 3) * 128 + k];
        float4 b = *(const float4*)&B_s[k * 128 + tx * 4];
        acc[0][0] = fmaf(a0, b.x, acc[0][0]); acc[0][1] = fmaf(a0, b.y, acc[0][1]);
        acc[0][2] = fmaf(a0, b.z, acc[0][2]); acc[0][3] = fmaf(a0, b.w, acc[0][3]);
        acc[1][0] = fmaf(a1, b.x, acc[1][0]); acc[1][1] = fmaf(a1, b.y, acc[1][1]);
        acc[1][2] = fmaf(a1, b.z, acc[1][2]); acc[1][3] = fmaf(a1, b.w, acc[1][3]);
        acc[2][0] = fmaf(a2, b.x, acc[2][0]); acc[2][1] = fmaf(a2, b.y, acc[2][1]);
        acc[2][2] = fmaf(a2, b.z, acc[2][2]); acc[2][3] = fmaf(a2, b.w, acc[2][3]);
        acc[3][0] = fmaf(a3, b.x, acc[3][0]); acc[3][1] = fmaf(a3, b.y, acc[3][1]);
        acc[3][2] = fmaf(a3, b.z, acc[3][2]); acc[3][3] = fmaf(a3, b.w, acc[3][3]);
    }

#pragma unroll
    for (int r = 0; r < 4; r++) {
        float4 v = make_float4(acc[r][0], acc[r][1], acc[r][2], acc[r][3]);
        *(float4*)&C[(row0 + ty * 4 + r) * OUTD + tx * 4] = v;
    }
}

// =====================================================================
// Kernel 1b: aR[j,h] = sum_d a[d] * R[j,h,d].  grid 32 x 128 threads.
// =====================================================================
__global__ __launch_bounds__(128) void ar_kernel()
{
    int t = blockIdx.x * 128 + threadIdx.x;   // [0,4096)
    int j = t >> 2, h = t & 3;
    const float4* row = (const float4*)&g_R[j * OUTD + h * DD];
    float s = 0.f;
#pragma unroll
    for (int k = 0; k < 8; k++) {
        float4 r = row[k];
        s += c_a[k * 4 + 0] * r.x + c_a[k * 4 + 1] * r.y +
             c_a[k * 4 + 2] * r.z + c_a[k * 4 + 3] * r.w;
    }
    g_aR[t] = s;
}

// =====================================================================
// Kernel 2: attention + softmax + aggregate + LayerNorm + ReLU.
// 128 blocks, 256 threads (8 warps, warp w owns row i = bx*8+w).
// =====================================================================
__device__ __forceinline__ unsigned smem_u32(const void* p)
{
    unsigned r;
    asm("{ .reg .u64 t; cvta.to.shared.u64 t, %1; cvt.u32.u64 %0, t; }"
        : "=r"(r) : "l"(p));
    return r;
}
__device__ __forceinline__ void cp16(float* dst, const float* src)
{
    unsigned d = smem_u32(dst);
    asm volatile("cp.async.cg.shared.global [%0], [%1], 16;" :: "r"(d), "l"(src));
}

// smem layout (floats):
//   R_s [2][TJ][RPAD] : 16896
//   V_s [2][TJ][128]  : 16384
//   w_s [8][4][WPAD]  : 2176
//   L_s [8][128]      : 1024
//   a_s [32]          : 32
#define SM_R 0
#define SM_V (2 * TJ * RPAD)
#define SM_W (SM_V + 2 * TJ * 128)
#define SM_L (SM_W + 8 * 4 * WPAD)
#define SM_A (SM_L + 8 * 128)
#define GAT_SMEM_FLOATS (SM_A + 32)

__global__ __launch_bounds__(256, 1) void gat_kernel(
    const int* __restrict__ adj,
    const float* __restrict__ a_g,
    const float* __restrict__ ln_g,
    const float* __restrict__ ln_b,
    float* __restrict__ out)
{
    extern __shared__ float sm[];
    float* R_s = sm + SM_R;
    float* V_s = sm + SM_V;
    float* w_s = sm + SM_W;
    float* L_s = sm + SM_L;
    float* a_s = sm + SM_A;

    const int tid = threadIdx.x, lane = tid & 31, wid = tid >> 5;
    const int i = blockIdx.x * 8 + wid;
    const int myh = lane >> 3;            // head owned in agg/epilogue

    // stage L rows for this block + a vector
    {
        int r = tid >> 5, c4 = tid & 31;  // exactly 256 float4 = 8*128 floats
        *(float4*)&L_s[r * 128 + c4 * 4] =
            *(const float4*)&g_L[(blockIdx.x * 8 + r) * OUTD + c4 * 4];
        if (tid < 32) a_s[tid] = a_g[tid];
    }

    // prologue: issue tile 0 loads
    {
        const int jb = 0;
#pragma unroll
        for (int u = 0; u < 8; u++) {
            int id = tid + u * 256; int r = id >> 5, c4 = id & 31;
            cp16(&R_s[r * RPAD + c4 * 4], &g_R[(jb + r) * OUTD + c4 * 4]);
        }
#pragma unroll
        for (int u = 0; u < 8; u++) {
            int id = tid + u * 256; int r = id >> 5, c4 = id & 31;
            cp16(&V_s[r * 128 + c4 * 4], &g_V[(jb + r) * OUTD + c4 * 4]);
        }
        asm volatile("cp.async.commit_group;" ::: "memory");
    }
    __syncthreads();   // L_s / a_s visible

    // aL[h] = sum_d a[d]*L[i,h,d] (replicated across warp)
    float aL[4];
#pragma unroll
    for (int h = 0; h < 4; h++) {
        float v = a_s[lane] * L_s[wid * 128 + h * 32 + lane];
#pragma unroll
        for (int o = 16; o; o >>= 1) v += __shfl_xor_sync(0xffffffffu, v, o);
        aL[h] = v;
    }

    float acc0 = 0.f, acc1 = 0.f, acc2 = 0.f, acc3 = 0.f;
    float mh[4] = { -1e30f, -1e30f, -1e30f, -1e30f };
    float sh[4] = { 0.f, 0.f, 0.f, 0.f };

    for (int t = 0; t < NT; t++) {
        const int b = t & 1;
        if (t + 1 < NT) {
            const int jb = (t + 1) * TJ;
            float* Rd = &R_s[(b ^ 1) * TJ * RPAD];
            float* Vd = &V_s[(b ^ 1) * TJ * 128];
#pragma unroll
            for (int u = 0; u < 8; u++) {
                int id = tid + u * 256; int r = id >> 5, c4 = id & 31;
                cp16(&Rd[r * RPAD + c4 * 4], &g_R[(jb + r) * OUTD + c4 * 4]);
            }
#pragma unroll
            for (int u = 0; u < 8; u++) {
                int id = tid + u * 256; int r = id >> 5, c4 = id & 31;
                cp16(&Vd[r * 128 + c4 * 4], &g_V[(jb + r) * OUTD + c4 * 4]);
            }
            asm volatile("cp.async.commit_group;" ::: "memory");
            asm volatile("cp.async.wait_group 1;" ::: "memory");
        } else {
            asm volatile("cp.async.wait_group 0;" ::: "memory");
        }
        __syncthreads();   // current tile (buf b) ready for everyone

        const float* Rb = &R_s[b * TJ * RPAD];
        const float* Vb = &V_s[b * TJ * 128];
        const int jb = t * TJ;

        const int av0 = adj[i * NN + jb + lane];
        const int av1 = adj[i * NN + jb + 32 + lane];

#pragma unroll
        for (int h = 0; h < 4; h++) {
            // L[i,h,:] into registers (broadcast loads)
            float Lr[32];
#pragma unroll
            for (int c4 = 0; c4 < 8; c4++) {
                float4 l4 = *(const float4*)&L_s[wid * 128 + h * 32 + c4 * 4];
                Lr[c4 * 4 + 0] = l4.x; Lr[c4 * 4 + 1] = l4.y;
                Lr[c4 * 4 + 2] = l4.z; Lr[c4 * 4 + 3] = l4.w;
            }
            float ev[2];
#pragma unroll
            for (int q = 0; q < 2; q++) {
                const float* Rrow = &Rb[(q * 32 + lane) * RPAD + h * 32];
                float e0 = 0.f, e1 = 0.f, e2 = 0.f, e3 = 0.f;
#pragma unroll
                for (int d4 = 0; d4 < 8; d4++) {
                    float4 r4 = *(const float4*)&Rrow[d4 * 4];
                    float p0 = Lr[d4 * 4 + 0] + r4.x;
                    float p1 = Lr[d4 * 4 + 1] + r4.y;
                    float p2 = Lr[d4 * 4 + 2] + r4.z;
                    float p3 = Lr[d4 * 4 + 3] + r4.w;
                    e0 = fmaf(c_a[d4 * 4 + 0], fabsf(p0), e0);
                    e1 = fmaf(c_a[d4 * 4 + 1], fabsf(p1), e1);
                    e2 = fmaf(c_a[d4 * 4 + 2], fabsf(p2), e2);
                    e3 = fmaf(c_a[d4 * 4 + 3], fabsf(p3), e3);
                }
                float aRj = g_aR[(jb + q * 32 + lane) * 4 + h];
                float e = 0.6f * (aL[h] + aRj) + 0.4f * ((e0 + e1) + (e2 + e3));
                int av = q ? av1 : av0;
                ev[q] = av ? e : -1e9f;
            }
            // online softmax update for head h
            float tmax = fmaxf(ev[0], ev[1]);
#pragma unroll
            for (int o = 16; o; o >>= 1)
                tmax = fmaxf(tmax, __shfl_xor_sync(0xffffffffu, tmax, o));
            float mnew = fmaxf(mh[h], tmax);
            float fsc = __expf(mh[h] - mnew);
            float w0 = __expf(ev[0] - mnew);
            float w1 = __expf(ev[1] - mnew);
            float tsum = w0 + w1;
#pragma unroll
            for (int o = 16; o; o >>= 1)
                tsum += __shfl_xor_sync(0xffffffffu, tsum, o);
            sh[h] = sh[h] * fsc + tsum;
            mh[h] = mnew;
            if (myh == h) { acc0 *= fsc; acc1 *= fsc; acc2 *= fsc; acc3 *= fsc; }
            w_s[(wid * 4 + h) * WPAD + lane] = w0;
            w_s[(wid * 4 + h) * WPAD + 32 + lane] = w1;
        }
        __syncwarp();

        // aggregate: lane owns columns lane*4 .. lane*4+3 (head myh)
        const float* wrow = &w_s[(wid * 4 + myh) * WPAD];
        const int cc = lane * 4;
#pragma unroll 4
        for (int j4 = 0; j4 < TJ / 4; j4++) {
            float4 wv = *(const float4*)&wrow[j4 * 4];
            float4 v0 = *(const float4*)&Vb[(j4 * 4 + 0) * 128 + cc];
            float4 v1 = *(const float4*)&Vb[(j4 * 4 + 1) * 128 + cc];
            float4 v2 = *(const float4*)&Vb[(j4 * 4 + 2) * 128 + cc];
            float4 v3 = *(const float4*)&Vb[(j4 * 4 + 3) * 128 + cc];
            acc0 = fmaf(wv.x, v0.x, acc0); acc1 = fmaf(wv.x, v0.y, acc1);
            acc2 = fmaf(wv.x, v0.z, acc2); acc3 = fmaf(wv.x, v0.w, acc3);
            acc0 = fmaf(wv.y, v1.x, acc0); acc1 = fmaf(wv.y, v1.y, acc1);
            acc2 = fmaf(wv.y, v1.z, acc2); acc3 = fmaf(wv.y, v1.w, acc3);
            acc0 = fmaf(wv.z, v2.x, acc0); acc1 = fmaf(wv.z, v2.y, acc1);
            acc2 = fmaf(wv.z, v2.z, acc2); acc3 = fmaf(wv.z, v2.w, acc3);
            acc0 = fmaf(wv.w, v3.x, acc0); acc1 = fmaf(wv.w, v3.y, acc1);
            acc2 = fmaf(wv.w, v3.z, acc2); acc3 = fmaf(wv.w, v3.w, acc3);
        }
        __syncthreads();   // everyone done with buffer b before it is refilled
    }

    // epilogue: normalize, LayerNorm, ReLU
    float inv = 1.0f / sh[myh];
    float x0 = acc0 * inv, x1 = acc1 * inv, x2 = acc2 * inv, x3 = acc3 * inv;
    float ssum = x0 + x1 + x2 + x3;
    float sqs  = x0 * x0 + x1 * x1 + x2 * x2 + x3 * x3;
#pragma unroll
    for (int o = 16; o; o >>= 1) {
        ssum += __shfl_xor_sync(0xffffffffu, ssum, o);
        sqs  += __shfl_xor_sync(0xffffffffu, sqs, o);
    }
    float mu   = ssum * (1.0f / 128.0f);
    float var  = sqs * (1.0f / 128.0f) - mu * mu;
    float rstd = rsqrtf(var + 1e-5f);
    float4 g4 = *(const float4*)&ln_g[lane * 4];
    float4 b4 = *(const float4*)&ln_b[lane * 4];
    float y0 = fmaxf((x0 - mu) * rstd * g4.x + b4.x, 0.f);
    float y1 = fmaxf((x1 - mu) * rstd * g4.y + b4.y, 0.f);
    float y2 = fmaxf((x2 - mu) * rstd * g4.z + b4.z, 0.f);
    float y3 = fmaxf((x3 - mu) * rstd * g4.w + b4.w, 0.f);
    *(float4*)&out[i * OUTD + lane * 4] = make_float4(y0, y1, y2, y3);
}

// =====================================================================
extern "C" void kernel_launch(void* const* d_in, const int* in_sizes, int n_in,
                              void* d_out, int out_size)
{
    const float* h   = (const float*)d_in[0];
    const int*   adj = (const int*)d_in[1];
    const float* Wl  = (const float*)d_in[2];
    const float* Wr  = (const float*)d_in[3];
    const float* Wv  = (const float*)d_in[4];
    const float* a   = (const float*)d_in[5];
    const float* g   = (const float*)d_in[6];
    const float* b   = (const float*)d_in[7];
    float* out = (float*)d_out;

    const int gemm_smem = (32 * 128 + 128 * 128) * (int)sizeof(float);   // 80KB
    const int gat_smem  = GAT_SMEM_FLOATS * (int)sizeof(float);          // ~143KB

    cudaFuncSetAttribute(gemm_kernel,
                         cudaFuncAttributeMaxDynamicSharedMemorySize, gemm_smem);
    cudaFuncSetAttribute(gat_kernel,
                         cudaFuncAttributeMaxDynamicSharedMemorySize, gat_smem);

    cudaMemcpyToSymbolAsync(c_a, a, DD * sizeof(float), 0,
                            cudaMemcpyDeviceToDevice, 0);

    gemm_kernel<<<dim3(32, 3), 256, gemm_smem>>>(h, Wl, Wr, Wv);
    ar_kernel<<<32, 128>>>();
    gat_kernel<<<128, 256, gat_smem>>>(adj, a, g, b, out);
}

// round 2
// speedup vs baseline: 1.0898x; 1.0898x over previous
#include <cuda_runtime.h>
#include <math.h>

#define NN   1024
#define OUTD 128
#define TJ   64
#define NT   16
#define RPAD 132
#define WP   68
#define OPAD 132

#define ABSM 0x7FFFFFFF7FFFFFFFULL

typedef unsigned long long u64;

// ---- scratch ----
__device__ __align__(16) float g_L[NN * OUTD];
__device__ __align__(16) float g_R[NN * OUTD];
__device__ __align__(16) float g_V[NN * OUTD];

__constant__ __align__(16) float c_a[32];

// ---- f32x2 helpers (sm_10x packed fp32) ----
__device__ __forceinline__ u64 f2add(u64 a, u64 b) {
    u64 d; asm("add.rn.f32x2 %0,%1,%2;" : "=l"(d) : "l"(a), "l"(b)); return d;
}
__device__ __forceinline__ u64 f2mul(u64 a, u64 b) {
    u64 d; asm("mul.rn.f32x2 %0,%1,%2;" : "=l"(d) : "l"(a), "l"(b)); return d;
}
__device__ __forceinline__ u64 f2fma(u64 a, u64 b, u64 c) {
    u64 d; asm("fma.rn.f32x2 %0,%1,%2,%3;" : "=l"(d) : "l"(a), "l"(b), "l"(c)); return d;
}
__device__ __forceinline__ u64 f2pack(float x, float y) {
    u64 d; asm("mov.b64 %0,{%1,%2};" : "=l"(d) : "f"(x), "f"(y)); return d;
}
__device__ __forceinline__ float2 f2unpack(u64 v) {
    float x, y; asm("mov.b64 {%0,%1},%2;" : "=f"(x), "=f"(y) : "l"(v));
    return make_float2(x, y);
}
__device__ __forceinline__ u64 a2c(int k) { return *(const u64*)&c_a[2 * k]; }

// =====================================================================
// Kernel 1: C = h @ W for W in {W_l, W_r, W_v}. BM=16, BN=128, K=128.
// grid (64, 3), 256 threads. smem = 16*128 + 128*128 floats = 72KB.
// =====================================================================
__global__ __launch_bounds__(256) void gemm_kernel(
    const float* __restrict__ H,
    const float* __restrict__ Wl,
    const float* __restrict__ Wr,
    const float* __restrict__ Wv)
{
    extern __shared__ float sm[];
    float* A_s = sm;              // [16][128]
    float* B_s = sm + 16 * 128;   // [128][128]

    const int tid = threadIdx.x;
    const int mat = blockIdx.y;
    const float* W = (mat == 0) ? Wl : ((mat == 1) ? Wr : Wv);
    float* C = (mat == 0) ? g_L : ((mat == 1) ? g_R : g_V);
    const int row0 = blockIdx.x * 16;

#pragma unroll
    for (int u = 0; u < 2; u++) {
        int id = tid + u * 256;        // [0,512) float4
        int r = id >> 5, c4 = id & 31;
        *(float4*)&A_s[r * 128 + c4 * 4] =
            *(const float4*)&H[(row0 + r) * 128 + c4 * 4];
    }
#pragma unroll
    for (int u = 0; u < 16; u++) {
        int id = tid + u * 256;        // [0,4096)
        int r = id >> 5, c4 = id & 31;
        *(float4*)&B_s[r * 128 + c4 * 4] =
            *(const float4*)&W[r * OUTD + c4 * 4];
    }
    __syncthreads();

    const int ty = tid >> 5, tx = tid & 31;   // 2 rows x 4 cols per thread
    const int r0 = ty * 2;
    float acc[2][4];
#pragma unroll
    for (int r = 0; r < 2; r++)
#pragma unroll
        for (int c = 0; c < 4; c++) acc[r][c] = 0.f;

#pragma unroll 8
    for (int k = 0; k < 128; k++) {
        float a0 = A_s[(r0 + 0) * 128 + k];
        float a1 = A_s[(r0 + 1) * 128 + k];
        float4 b = *(const float4*)&B_s[k * 128 + tx * 4];
        acc[0][0] = fmaf(a0, b.x, acc[0][0]); acc[0][1] = fmaf(a0, b.y, acc[0][1]);
        acc[0][2] = fmaf(a0, b.z, acc[0][2]); acc[0][3] = fmaf(a0, b.w, acc[0][3]);
        acc[1][0] = fmaf(a1, b.x, acc[1][0]); acc[1][1] = fmaf(a1, b.y, acc[1][1]);
        acc[1][2] = fmaf(a1, b.z, acc[1][2]); acc[1][3] = fmaf(a1, b.w, acc[1][3]);
    }

#pragma unroll
    for (int r = 0; r < 2; r++) {
        float4 v = make_float4(acc[r][0], acc[r][1], acc[r][2], acc[r][3]);
        *(float4*)&C[(row0 + r0 + r) * OUTD + tx * 4] = v;
    }
}

// =====================================================================
// Kernel 2: attention + softmax + aggregate + LayerNorm + ReLU.
// 128 blocks x 256 threads (8 warps). Block owns 8 rows i.
// Score: warp (h = wid>>1, g = wid&1) -> rows 4g..4g+3, head h, all 64 j.
//        R[j,h,:] in registers (reused across 4 rows), f32x2 packed math.
// Agg:   warp (h = wid>>1, ds = wid&1) -> 16 d-cols, lane = (i, c).
// =====================================================================
__device__ __forceinline__ unsigned smem_u32(const void* p)
{
    unsigned r;
    asm("{ .reg .u64 t; cvta.to.shared.u64 t, %1; cvt.u32.u64 %0, t; }"
        : "=r"(r) : "l"(p));
    return r;
}
__device__ __forceinline__ void cp16(float* dst, const float* src)
{
    unsigned d = smem_u32(dst);
    asm volatile("cp.async.cg.shared.global [%0], [%1], 16;" :: "r"(d), "l"(src));
}

// smem layout (floats)
#define SM_R 0
#define SM_V (SM_R + 2 * TJ * RPAD)            // 16896
#define SM_W (SM_V + 2 * TJ * 128)             // 33280
#define SM_L (SM_W + 32 * WP)                  // 35456
#define SM_F (SM_L + 8 * 128)                  // 36480 fsc[8][4]
#define SM_S (SM_F + 32)                       // 36512 s[8][4]
#define SM_O (SM_S + 32)                       // 36544 out_s[8][OPAD]
#define GAT_SMEM_FLOATS (SM_O + 8 * OPAD)      // 37600

__device__ __forceinline__ void prefetch_tile(float* Rd, float* Vd, int jb, int tid)
{
#pragma unroll
    for (int u = 0; u < 8; u++) {
        int id = tid + u * 256; int r = id >> 5, c4 = id & 31;
        cp16(&Rd[r * RPAD + c4 * 4], &g_R[(jb + r) * OUTD + c4 * 4]);
    }
#pragma unroll
    for (int u = 0; u < 8; u++) {
        int id = tid + u * 256; int r = id >> 5, c4 = id & 31;
        cp16(&Vd[r * 128 + c4 * 4], &g_V[(jb + r) * OUTD + c4 * 4]);
    }
}

__global__ __launch_bounds__(256, 1) void gat_kernel(
    const int* __restrict__ adj,
    const float* __restrict__ ln_g,
    const float* __restrict__ ln_b,
    float* __restrict__ out)
{
    extern __shared__ float sm[];
    float* R_s   = sm + SM_R;
    float* V_s   = sm + SM_V;
    float* w_s   = sm + SM_W;
    float* L_s   = sm + SM_L;
    float* fsc_s = sm + SM_F;
    float* s_s   = sm + SM_S;
    float* out_s = sm + SM_O;

    const int tid = threadIdx.x, lane = tid & 31, wid = tid >> 5;
    const int h  = wid >> 1;        // head (both roles)
    const int g  = wid & 1;         // score: i-group
    const int ds = wid & 1;         // agg: d-half within head
    const int ai = lane >> 2;       // agg: row index 0..7
    const int ac = lane & 3;        // agg: col group 0..3
    const int colb = h * 32 + ds * 16 + ac * 4;
    const int row0 = blockIdx.x * 8;

    // stage L rows for this block (8x128 = 256 float4, 1 per thread)
    {
        int r = tid >> 5, c4 = tid & 31;
        *(float4*)&L_s[r * 128 + c4 * 4] =
            *(const float4*)&g_L[(row0 + r) * OUTD + c4 * 4];
    }
    // prefetch tile 0
    prefetch_tile(R_s, V_s, 0, tid);
    asm volatile("cp.async.commit_group;" ::: "memory");
    __syncthreads();   // L_s visible

    // aL[ii] = sum_d a[d]*L[i,h,d] (lane-replicated via broadcast loads)
    float aL[4];
#pragma unroll
    for (int ii = 0; ii < 4; ii++) {
        const ulonglong2* Lp = (const ulonglong2*)&L_s[(4 * g + ii) * 128 + h * 32];
        u64 sa = 0ULL, sb = 0ULL;
#pragma unroll
        for (int k = 0; k < 8; k++) {
            ulonglong2 l2 = Lp[k];
            sa = f2fma(a2c(2 * k), l2.x, sa);
            sb = f2fma(a2c(2 * k + 1), l2.y, sb);
        }
        float2 u = f2unpack(f2add(sa, sb));
        aL[ii] = u.x + u.y;
    }

    float m[4] = { -1e30f, -1e30f, -1e30f, -1e30f };
    float s[4] = { 0.f, 0.f, 0.f, 0.f };
    u64 accA0 = 0ULL, accA1 = 0ULL, accB0 = 0ULL, accB1 = 0ULL;

    for (int t = 0; t < NT; t++) {
        const int b = t & 1;
        if (t + 1 < NT) {
            prefetch_tile(&R_s[(b ^ 1) * TJ * RPAD], &V_s[(b ^ 1) * TJ * 128],
                          (t + 1) * TJ, tid);
            asm volatile("cp.async.commit_group;" ::: "memory");
            asm volatile("cp.async.wait_group 1;" ::: "memory");
        } else {
            asm volatile("cp.async.wait_group 0;" ::: "memory");
        }
        __syncthreads();   // (A) tile b ready

        // ================= SCORE PHASE =================
        const float* Rb = R_s + b * TJ * RPAD;
        const int jb = t * TJ;

        int av0[4], av1[4];
#pragma unroll
        for (int ii = 0; ii < 4; ii++) {
            const int* arow = adj + (row0 + 4 * g + ii) * NN + jb;
            av0[ii] = arow[lane];
            av1[ii] = arow[lane + 32];
        }

        float e0[4], e1[4], aRv[2];
#pragma unroll
        for (int jj = 0; jj < 2; jj++) {
            u64 R2[16];
            const ulonglong2* Rp =
                (const ulonglong2*)&Rb[(jj * 32 + lane) * RPAD + h * 32];
#pragma unroll
            for (int mr = 0; mr < 8; mr++) {
                ulonglong2 tt = Rp[mr];
                R2[2 * mr] = tt.x; R2[2 * mr + 1] = tt.y;
            }
            // aR for this lane's j
            u64 ra = 0ULL, rb = 0ULL;
#pragma unroll
            for (int k = 0; k < 8; k++) {
                ra = f2fma(a2c(2 * k), R2[2 * k], ra);
                rb = f2fma(a2c(2 * k + 1), R2[2 * k + 1], rb);
            }
            float2 ur = f2unpack(f2add(ra, rb));
            aRv[jj] = ur.x + ur.y;

#pragma unroll
            for (int ii = 0; ii < 4; ii++) {
                const ulonglong2* Lp =
                    (const ulonglong2*)&L_s[(4 * g + ii) * 128 + h * 32];
                u64 sa = 0ULL, sb = 0ULL;
#pragma unroll
                for (int k = 0; k < 8; k++) {
                    ulonglong2 l2 = Lp[k];
                    u64 p0 = f2add(l2.x, R2[2 * k]) & ABSM;
                    u64 p1 = f2add(l2.y, R2[2 * k + 1]) & ABSM;
                    sa = f2fma(a2c(2 * k), p0, sa);
                    sb = f2fma(a2c(2 * k + 1), p1, sb);
                }
                float2 us = f2unpack(f2add(sa, sb));
                float e = 0.6f * (aL[ii] + aRv[jj]) + 0.4f * (us.x + us.y);
                int av = jj ? av1[ii] : av0[ii];
                e = av ? e : -1e9f;
                if (jj == 0) e0[ii] = e; else e1[ii] = e;
            }
        }

        // online softmax (4 independent reduction chains)
        float tm[4];
#pragma unroll
        for (int ii = 0; ii < 4; ii++) {
            float v = fmaxf(e0[ii], e1[ii]);
#pragma unroll
            for (int o = 16; o; o >>= 1)
                v = fmaxf(v, __shfl_xor_sync(0xffffffffu, v, o));
            tm[ii] = v;
        }
#pragma unroll
        for (int ii = 0; ii < 4; ii++) {
            float mn = fmaxf(m[ii], tm[ii]);
            float fs = __expf(m[ii] - mn);
            float w0 = __expf(e0[ii] - mn);
            float w1 = __expf(e1[ii] - mn);
            m[ii] = mn;
            int rw = ((4 * g + ii) * 4 + h) * WP;
            w_s[rw + lane] = w0;
            w_s[rw + 32 + lane] = w1;
            float ts = w0 + w1;
#pragma unroll
            for (int o = 16; o; o >>= 1)
                ts += __shfl_xor_sync(0xffffffffu, ts, o);
            s[ii] = s[ii] * fs + ts;
            if (lane == 0) fsc_s[(4 * g + ii) * 4 + h] = fs;
        }
        __syncthreads();   // (B) weights ready

        // ================= AGG PHASE =================
        {
            const float* Vb = V_s + b * TJ * 128;
            float fs = fsc_s[ai * 4 + h];
            u64 fs2 = f2pack(fs, fs);
            accA0 = f2mul(accA0, fs2); accA1 = f2mul(accA1, fs2);
            accB0 = f2mul(accB0, fs2); accB1 = f2mul(accB1, fs2);
            const float* wrow = w_s + (ai * 4 + h) * WP;
#pragma unroll 4
            for (int j4 = 0; j4 < 16; j4++) {
                float4 w4 = *(const float4*)&wrow[j4 * 4];
                const float* vb0 = Vb + (j4 * 4) * 128 + colb;
                ulonglong2 v0 = *(const ulonglong2*)(vb0);
                ulonglong2 v1 = *(const ulonglong2*)(vb0 + 128);
                ulonglong2 v2 = *(const ulonglong2*)(vb0 + 256);
                ulonglong2 v3 = *(const ulonglong2*)(vb0 + 384);
                u64 wp0 = f2pack(w4.x, w4.x);
                u64 wp1 = f2pack(w4.y, w4.y);
                u64 wp2 = f2pack(w4.z, w4.z);
                u64 wp3 = f2pack(w4.w, w4.w);
                accA0 = f2fma(wp0, v0.x, accA0); accA1 = f2fma(wp0, v0.y, accA1);
                accB0 = f2fma(wp1, v1.x, accB0); accB1 = f2fma(wp1, v1.y, accB1);
                accA0 = f2fma(wp2, v2.x, accA0); accA1 = f2fma(wp2, v2.y, accA1);
                accB0 = f2fma(wp3, v3.x, accB0); accB1 = f2fma(wp3, v3.y, accB1);
            }
        }
        __syncthreads();   // (C) buffers/weights free for next tile
    }

    // final softmax denominators
    if (lane == 0) {
#pragma unroll
        for (int ii = 0; ii < 4; ii++)
            s_s[(4 * g + ii) * 4 + h] = s[ii];
    }
    __syncthreads();

    // normalize + stage to out_s
    {
        float inv = 1.0f / s_s[ai * 4 + h];
        float2 t0 = f2unpack(f2add(accA0, accB0));
        float2 t1 = f2unpack(f2add(accA1, accB1));
        *(float4*)&out_s[ai * OPAD + colb] =
            make_float4(t0.x * inv, t0.y * inv, t1.x * inv, t1.y * inv);
    }
    __syncthreads();

    // LayerNorm + ReLU: warp wid owns row wid
    {
        float4 x = *(const float4*)&out_s[wid * OPAD + lane * 4];
        float ssum = x.x + x.y + x.z + x.w;
        float sqs  = x.x * x.x + x.y * x.y + x.z * x.z + x.w * x.w;
#pragma unroll
        for (int o = 16; o; o >>= 1) {
            ssum += __shfl_xor_sync(0xffffffffu, ssum, o);
            sqs  += __shfl_xor_sync(0xffffffffu, sqs, o);
        }
        float mu   = ssum * (1.0f / 128.0f);
        float var  = sqs * (1.0f / 128.0f) - mu * mu;
        float rstd = rsqrtf(var + 1e-5f);
        float4 g4 = *(const float4*)&ln_g[lane * 4];
        float4 b4 = *(const float4*)&ln_b[lane * 4];
        float y0 = fmaxf((x.x - mu) * rstd * g4.x + b4.x, 0.f);
        float y1 = fmaxf((x.y - mu) * rstd * g4.y + b4.y, 0.f);
        float y2 = fmaxf((x.z - mu) * rstd * g4.z + b4.z, 0.f);
        float y3 = fmaxf((x.w - mu) * rstd * g4.w + b4.w, 0.f);
        *(float4*)&out[(row0 + wid) * OUTD + lane * 4] =
            make_float4(y0, y1, y2, y3);
    }
}

// =====================================================================
extern "C" void kernel_launch(void* const* d_in, const int* in_sizes, int n_in,
                              void* d_out, int out_size)
{
    const float* h   = (const float*)d_in[0];
    const int*   adj = (const int*)d_in[1];
    const float* Wl  = (const float*)d_in[2];
    const float* Wr  = (const float*)d_in[3];
    const float* Wv  = (const float*)d_in[4];
    const float* a   = (const float*)d_in[5];
    const float* g   = (const float*)d_in[6];
    const float* b   = (const float*)d_in[7];
    float* out = (float*)d_out;

    const int gemm_smem = (16 * 128 + 128 * 128) * (int)sizeof(float);   // 72KB
    const int gat_smem  = GAT_SMEM_FLOATS * (int)sizeof(float);          // ~147KB

    cudaFuncSetAttribute(gemm_kernel,
                         cudaFuncAttributeMaxDynamicSharedMemorySize, gemm_smem);
    cudaFuncSetAttribute(gat_kernel,
                         cudaFuncAttributeMaxDynamicSharedMemorySize, gat_smem);

    cudaMemcpyToSymbolAsync(c_a, a, 32 * sizeof(float), 0,
                            cudaMemcpyDeviceToDevice, 0);

    gemm_kernel<<<dim3(64, 3), 256, gemm_smem>>>(h, Wl, Wr, Wv);
    gat_kernel<<<128, 256, gat_smem>>>(adj, g, b, out);
}

// round 3
// speedup vs baseline: 1.3169x; 1.2084x over previous
#include <cuda_runtime.h>
#include <math.h>

#define NN   1024
#define OUTD 128
#define TJ   64
#define NT   16
#define RPAD 132
#define VPAD 132
#define LPAD 132
#define OPAD 132
#define WP   67

#define ABSM 0x7FFFFFFF7FFFFFFFULL

typedef unsigned long long u64;

// ---- scratch ----
__device__ __align__(16) float g_L[NN * OUTD];
__device__ __align__(16) float g_R[NN * OUTD];
__device__ __align__(16) float g_V[NN * OUTD];
__device__ __align__(16) float g_aR[4 * NN];   // [h][j]

__constant__ __align__(16) float c_a[32];

// ---- f32x2 helpers ----
__device__ __forceinline__ u64 f2add(u64 a, u64 b) {
    u64 d; asm("add.rn.f32x2 %0,%1,%2;" : "=l"(d) : "l"(a), "l"(b)); return d;
}
__device__ __forceinline__ u64 f2fma(u64 a, u64 b, u64 c) {
    u64 d; asm("fma.rn.f32x2 %0,%1,%2,%3;" : "=l"(d) : "l"(a), "l"(b), "l"(c)); return d;
}
__device__ __forceinline__ u64 f2pack(float x, float y) {
    u64 d; asm("mov.b64 %0,{%1,%2};" : "=l"(d) : "f"(x), "f"(y)); return d;
}
__device__ __forceinline__ float2 f2unpack(u64 v) {
    float x, y; asm("mov.b64 {%0,%1},%2;" : "=f"(x), "=f"(y) : "l"(v));
    return make_float2(x, y);
}
__device__ __forceinline__ u64 a2c(int k) { return *(const u64*)&c_a[2 * k]; }

// =====================================================================
// Kernel 1: C = h @ W, packed f32x2, BM=16, grid (64,3), 256 thr.
// For mat==1 (W_r) also writes g_aR[h][row] = sum_d a_d R[row, 32h+d].
// =====================================================================
__global__ __launch_bounds__(256) void gemm_kernel(
    const float* __restrict__ H,
    const float* __restrict__ Wl,
    const float* __restrict__ Wr,
    const float* __restrict__ Wv)
{
    extern __shared__ float sm[];
    float* A_s = sm;              // [16][128]
    float* B_s = sm + 16 * 128;   // [128][128]

    const int tid = threadIdx.x;
    const int mat = blockIdx.y;
    const float* W = (mat == 0) ? Wl : ((mat == 1) ? Wr : Wv);
    float* C = (mat == 0) ? g_L : ((mat == 1) ? g_R : g_V);
    const int row0 = blockIdx.x * 16;

#pragma unroll
    for (int u = 0; u < 2; u++) {
        int id = tid + u * 256;
        int r = id >> 5, c4 = id & 31;
        *(float4*)&A_s[r * 128 + c4 * 4] =
            *(const float4*)&H[(row0 + r) * 128 + c4 * 4];
    }
#pragma unroll
    for (int u = 0; u < 16; u++) {
        int id = tid + u * 256;
        int r = id >> 5, c4 = id & 31;
        *(float4*)&B_s[r * 128 + c4 * 4] =
            *(const float4*)&W[r * OUTD + c4 * 4];
    }
    __syncthreads();

    const int ty = tid >> 5, tx = tid & 31;
    const int r0 = ty * 2;
    u64 c00 = 0ULL, c01 = 0ULL, c10 = 0ULL, c11 = 0ULL;

#pragma unroll 8
    for (int k = 0; k < 128; k++) {
        float a0 = A_s[(r0 + 0) * 128 + k];
        float a1 = A_s[(r0 + 1) * 128 + k];
        ulonglong2 b2 = *(const ulonglong2*)&B_s[k * 128 + tx * 4];
        u64 ap0 = f2pack(a0, a0);
        u64 ap1 = f2pack(a1, a1);
        c00 = f2fma(ap0, b2.x, c00); c01 = f2fma(ap0, b2.y, c01);
        c10 = f2fma(ap1, b2.x, c10); c11 = f2fma(ap1, b2.y, c11);
    }

    float2 u00 = f2unpack(c00), u01 = f2unpack(c01);
    float2 u10 = f2unpack(c10), u11 = f2unpack(c11);
    float a0c[4] = { u00.x, u00.y, u01.x, u01.y };
    float a1c[4] = { u10.x, u10.y, u11.x, u11.y };

    *(float4*)&C[(row0 + r0 + 0) * OUTD + tx * 4] =
        make_float4(a0c[0], a0c[1], a0c[2], a0c[3]);
    *(float4*)&C[(row0 + r0 + 1) * OUTD + tx * 4] =
        make_float4(a1c[0], a1c[1], a1c[2], a1c[3]);

    if (mat == 1) {
        // aR epilogue: reduce a·R over the 8 lanes of each head
        const int hb = (tx & 7) * 4;
        float p0 = 0.f, p1 = 0.f;
#pragma unroll
        for (int c = 0; c < 4; c++) {
            float av = c_a[hb + c];
            p0 = fmaf(av, a0c[c], p0);
            p1 = fmaf(av, a1c[c], p1);
        }
#pragma unroll
        for (int o = 1; o < 8; o <<= 1) {
            p0 += __shfl_xor_sync(0xffffffffu, p0, o);
            p1 += __shfl_xor_sync(0xffffffffu, p1, o);
        }
        if ((tx & 7) == 0) {
            int h = tx >> 3;
            g_aR[h * NN + row0 + r0 + 0] = p0;
            g_aR[h * NN + row0 + r0 + 1] = p1;
        }
    }
}

// =====================================================================
// Kernel 2: 128 blocks x 512 threads (16 warps), 8 rows per block.
// Score: warp (h = wid&3, jq = wid>>2); lane = (j = jq*16 + lane>>1,
//        rh = lane&1 -> rows rh*4..rh*4+3). No online softmax.
// Agg:   warp (ah = wid&3, ds = wid>>2) -> cols [32ah+8ds, +8);
//        lane = (aj = lane>>1, arh = lane&1 -> 4 rows), accums in regs,
//        one cross-lane reduce at the end.
// =====================================================================
__device__ __forceinline__ unsigned smem_u32(const void* p)
{
    unsigned r;
    asm("{ .reg .u64 t; cvta.to.shared.u64 t, %1; cvt.u32.u64 %0, t; }"
        : "=r"(r) : "l"(p));
    return r;
}
__device__ __forceinline__ void cp16(float* dst, const float* src)
{
    unsigned d = smem_u32(dst);
    asm volatile("cp.async.cg.shared.global [%0], [%1], 16;" :: "r"(d), "l"(src));
}

// smem layout (floats)
#define SM_R  0
#define SM_V  (SM_R + 2 * TJ * RPAD)       // 16896
#define SM_AR (SM_V + 2 * TJ * VPAD)       // 33792
#define SM_W  (SM_AR + 2 * 4 * TJ)         // 34304
#define SM_L  (SM_W + 32 * WP)             // 36448
#define SM_SP (SM_L + 8 * LPAD)            // 37504  s_part[4jq][8row][4h]
#define SM_O  (SM_SP + 128)                // 37632
#define GAT_SMEM_FLOATS (SM_O + 8 * OPAD)  // 38688

__device__ __forceinline__ void prefetch_tile(float* sm, int buf, int jb, int tid)
{
    float* Rd = sm + SM_R + buf * TJ * RPAD;
    float* Vd = sm + SM_V + buf * TJ * VPAD;
#pragma unroll
    for (int u = 0; u < 4; u++) {
        int id = tid + u * 512; int r = id >> 5, c4 = id & 31;
        cp16(&Rd[r * RPAD + c4 * 4], &g_R[(jb + r) * OUTD + c4 * 4]);
    }
#pragma unroll
    for (int u = 0; u < 4; u++) {
        int id = tid + u * 512; int r = id >> 5, c4 = id & 31;
        cp16(&Vd[r * VPAD + c4 * 4], &g_V[(jb + r) * OUTD + c4 * 4]);
    }
    if (tid < 64) {
        int h = tid >> 4, c4 = tid & 15;
        cp16(&sm[SM_AR + buf * 256 + h * TJ + c4 * 4],
             &g_aR[h * NN + jb + c4 * 4]);
    }
}

__global__ __launch_bounds__(512, 1) void gat_kernel(
    const int* __restrict__ adj,
    const float* __restrict__ ln_g,
    const float* __restrict__ ln_b,
    float* __restrict__ out)
{
    extern __shared__ float sm[];
    float* w_s   = sm + SM_W;
    float* L_s   = sm + SM_L;
    float* sp_s  = sm + SM_SP;
    float* out_s = sm + SM_O;

    const int tid = threadIdx.x, lane = tid & 31, wid = tid >> 5;
    const int h  = wid & 3;         // head (both roles)
    const int jq = wid >> 2;        // score: j-quarter / agg: ds
    const int jg = jq * 16 + (lane >> 1);   // score: j within tile (0..63)
    const int rh = lane & 1;        // row half (both roles)
    const int aj = lane >> 1;       // agg: j16 index
    const int colb = h * 32 + jq * 8;       // agg col base
    const int row0 = blockIdx.x * 8;

    // prologue: prefetch tile 0, stage L
    prefetch_tile(sm, 0, 0, tid);
    asm volatile("cp.async.commit_group;" ::: "memory");
    if (tid < 256) {
        int r = tid >> 5, c4 = tid & 31;
        *(float4*)&L_s[r * LPAD + c4 * 4] =
            *(const float4*)&g_L[(row0 + r) * OUTD + c4 * 4];
    }
    __syncthreads();   // L_s ready

    // lin[ii] = 0.6 * (a . L[row, h-slice])
    float lin[4];
#pragma unroll
    for (int ii = 0; ii < 4; ii++) {
        const float* Lrow = &L_s[(rh * 4 + ii) * LPAD + h * 32];
        u64 sa = 0ULL, sb = 0ULL;
#pragma unroll
        for (int k = 0; k < 8; k++) {
            ulonglong2 l2 = *(const ulonglong2*)&Lrow[k * 4];
            sa = f2fma(a2c(2 * k), l2.x, sa);
            sb = f2fma(a2c(2 * k + 1), l2.y, sb);
        }
        float2 u = f2unpack(f2add(sa, sb));
        lin[ii] = 0.6f * (u.x + u.y);
    }

    // adj for tile 0
    int av[4];
#pragma unroll
    for (int ii = 0; ii < 4; ii++)
        av[ii] = adj[(row0 + rh * 4 + ii) * NN + jg];

    float s_acc[4] = { 0.f, 0.f, 0.f, 0.f };
    u64 acc[4][4];
#pragma unroll
    for (int r = 0; r < 4; r++)
#pragma unroll
        for (int c = 0; c < 4; c++) acc[r][c] = 0ULL;

    for (int t = 0; t < NT; t++) {
        const int b = t & 1;
        asm volatile("cp.async.wait_group 0;" ::: "memory");
        __syncthreads();   // (A) tile t ready; previous agg done

        if (t + 1 < NT) {
            prefetch_tile(sm, b ^ 1, (t + 1) * TJ, tid);
            asm volatile("cp.async.commit_group;" ::: "memory");
        }
        // next-tile adj
        int avn[4];
        if (t + 1 < NT) {
#pragma unroll
            for (int ii = 0; ii < 4; ii++)
                avn[ii] = adj[(row0 + rh * 4 + ii) * NN + (t + 1) * TJ + jg];
        }

        // ================= SCORE =================
        {
            const float* Rrow = sm + SM_R + b * TJ * RPAD + jg * RPAD + h * 32;
            u64 sa[4], sb[4];
#pragma unroll
            for (int ii = 0; ii < 4; ii++) { sa[ii] = 0ULL; sb[ii] = 0ULL; }
#pragma unroll
            for (int k = 0; k < 8; k++) {
                ulonglong2 r2 = *(const ulonglong2*)&Rrow[k * 4];
#pragma unroll
                for (int ii = 0; ii < 4; ii++) {
                    const ulonglong2 l2 = *(const ulonglong2*)
                        &L_s[(rh * 4 + ii) * LPAD + h * 32 + k * 4];
                    sa[ii] = f2fma(a2c(2 * k),
                                   f2add(l2.x, r2.x) & ABSM, sa[ii]);
                    sb[ii] = f2fma(a2c(2 * k + 1),
                                   f2add(l2.y, r2.y) & ABSM, sb[ii]);
                }
            }
            float ar6 = 0.6f * sm[SM_AR + b * 256 + h * TJ + jg];
#pragma unroll
            for (int ii = 0; ii < 4; ii++) {
                float2 u = f2unpack(f2add(sa[ii], sb[ii]));
                float e = fmaf(0.4f, u.x + u.y, lin[ii] + ar6);
                float w = av[ii] ? __expf(e) : 0.f;
                s_acc[ii] += w;
                w_s[((rh * 4 + ii) * 4 + h) * WP + jg] = w;
            }
        }
#pragma unroll
        for (int ii = 0; ii < 4; ii++) av[ii] = avn[ii];
        __syncthreads();   // (B) weights ready

        // ================= AGG =================
        {
            const float* Vb = sm + SM_V + b * TJ * VPAD;
#pragma unroll
            for (int jj = 0; jj < 4; jj++) {
                int j = jj * 16 + aj;
                const float* vrow = &Vb[j * VPAD + colb];
                ulonglong2 v0 = *(const ulonglong2*)(vrow);
                ulonglong2 v1 = *(const ulonglong2*)(vrow + 4);
#pragma unroll
                for (int r = 0; r < 4; r++) {
                    float w = w_s[((rh * 4 + r) * 4 + h) * WP + j];
                    u64 wp = f2pack(w, w);
                    acc[r][0] = f2fma(wp, v0.x, acc[r][0]);
                    acc[r][1] = f2fma(wp, v0.y, acc[r][1]);
                    acc[r][2] = f2fma(wp, v1.x, acc[r][2]);
                    acc[r][3] = f2fma(wp, v1.y, acc[r][3]);
                }
            }
        }
    }

    // ---- score sums: reduce over the 16 j-lanes (stride-2 groups) ----
#pragma unroll
    for (int ii = 0; ii < 4; ii++) {
#pragma unroll
        for (int o = 2; o < 32; o <<= 1)
            s_acc[ii] += __shfl_xor_sync(0xffffffffu, s_acc[ii], o);
    }
    if (lane < 2) {
#pragma unroll
        for (int ii = 0; ii < 4; ii++)
            sp_s[jq * 32 + (rh * 4 + ii) * 4 + h] = s_acc[ii];
    }
    __syncthreads();   // s_part complete; tile buffers no longer needed

    // ---- agg reduce over j-lanes, normalize, stage to out_s ----
#pragma unroll
    for (int r = 0; r < 4; r++)
#pragma unroll
        for (int c = 0; c < 4; c++) {
#pragma unroll
            for (int o = 2; o < 32; o <<= 1) {
                u64 other = __shfl_xor_sync(0xffffffffu, acc[r][c], o);
                acc[r][c] = f2add(acc[r][c], other);
            }
        }
    if (lane < 2) {
#pragma unroll
        for (int r = 0; r < 4; r++) {
            int row = rh * 4 + r;
            float s = sp_s[0 * 32 + row * 4 + h] + sp_s[1 * 32 + row * 4 + h]
                    + sp_s[2 * 32 + row * 4 + h] + sp_s[3 * 32 + row * 4 + h];
            float inv = 1.0f / s;
#pragma unroll
            for (int c = 0; c < 4; c++) {
                float2 u = f2unpack(acc[r][c]);
                *(float2*)&out_s[row * OPAD + colb + c * 2] =
                    make_float2(u.x * inv, u.y * inv);
            }
        }
    }
    __syncthreads();   // out_s complete

    // ---- LayerNorm + ReLU: warps 0..7, warp = row ----
    if (wid < 8) {
        float4 x = *(const float4*)&out_s[wid * OPAD + lane * 4];
        float ssum = x.x + x.y + x.z + x.w;
        float sqs  = x.x * x.x + x.y * x.y + x.z * x.z + x.w * x.w;
#pragma unroll
        for (int o = 16; o; o >>= 1) {
            ssum += __shfl_xor_sync(0xffffffffu, ssum, o);
            sqs  += __shfl_xor_sync(0xffffffffu, sqs, o);
        }
        float mu   = ssum * (1.0f / 128.0f);
        float var  = sqs * (1.0f / 128.0f) - mu * mu;
        float rstd = rsqrtf(var + 1e-5f);
        float4 g4 = *(const float4*)&ln_g[lane * 4];
        float4 b4 = *(const float4*)&ln_b[lane * 4];
        float y0 = fmaxf((x.x - mu) * rstd * g4.x + b4.x, 0.f);
        float y1 = fmaxf((x.y - mu) * rstd * g4.y + b4.y, 0.f);
        float y2 = fmaxf((x.z - mu) * rstd * g4.z + b4.z, 0.f);
        float y3 = fmaxf((x.w - mu) * rstd * g4.w + b4.w, 0.f);
        *(float4*)&out[(row0 + wid) * OUTD + lane * 4] =
            make_float4(y0, y1, y2, y3);
    }
}

// =====================================================================
extern "C" void kernel_launch(void* const* d_in, const int* in_sizes, int n_in,
                              void* d_out, int out_size)
{
    const float* h   = (const float*)d_in[0];
    const int*   adj = (const int*)d_in[1];
    const float* Wl  = (const float*)d_in[2];
    const float* Wr  = (const float*)d_in[3];
    const float* Wv  = (const float*)d_in[4];
    const float* a   = (const float*)d_in[5];
    const float* g   = (const float*)d_in[6];
    const float* b   = (const float*)d_in[7];
    float* out = (float*)d_out;

    const int gemm_smem = (16 * 128 + 128 * 128) * (int)sizeof(float);   // 72KB
    const int gat_smem  = GAT_SMEM_FLOATS * (int)sizeof(float);          // ~151KB

    cudaFuncSetAttribute(gemm_kernel,
                         cudaFuncAttributeMaxDynamicSharedMemorySize, gemm_smem);
    cudaFuncSetAttribute(gat_kernel,
                         cudaFuncAttributeMaxDynamicSharedMemorySize, gat_smem);

    cudaMemcpyToSymbolAsync(c_a, a, 32 * sizeof(float), 0,
                            cudaMemcpyDeviceToDevice, 0);

    gemm_kernel<<<dim3(64, 3), 256, gemm_smem>>>(h, Wl, Wr, Wv);
    gat_kernel<<<128, 512, gat_smem>>>(adj, g, b, out);
}